// round 4
// baseline (speedup 1.0000x reference)
#include <cuda_runtime.h>
#include <cstdint>
#include <math.h>

// ---------------------------------------------------------------------------
// Attention_37074157699274 — round 3: mma.sync tf32, 64x64 warp tiles,
// cp.async double-buffered staging (tcgen05 unavailable: harness PTX targets
// compute_103 without the 'a' feature set).
//   T1/T2: transpose weights -> [N,K] scratch
//   K1: qkv  = x @ W_qkv      tile 128x256, K=256
//   K2: attn per (b,p,h)
//   K3: out  = attn @ W_out+b tile 128x256, K=512
// ---------------------------------------------------------------------------

#define TOKENS   131072
#define GROUPS   4096
#define DIMX     256
#define NQKV     1536
#define INNER    512
#define HEADS    8
#define DH       64
#define ATT_SCALE 0.125f

__device__ float g_qkv [(size_t)TOKENS * NQKV];    // 805 MB
__device__ float g_attn[(size_t)TOKENS * INNER];   // 268 MB
__device__ float g_WqkvT[(size_t)NQKV * DIMX];
__device__ float g_WoutT[(size_t)DIMX * INNER];

// ------------------------- helpers ------------------------------------------

__device__ __forceinline__ uint32_t f2tf32(float x) {
    uint32_t u;
    asm("cvt.rna.tf32.f32 %0, %1;" : "=r"(u) : "f"(x));
    return u;
}
__device__ __forceinline__ float f2tf32f(float x) { return __uint_as_float(f2tf32(x)); }

__device__ __forceinline__ uint32_t smem_u32(const void* p) {
    uint32_t a;
    asm("{ .reg .u64 t; cvta.to.shared.u64 t, %1; cvt.u32.u64 %0, t; }"
        : "=r"(a) : "l"(p));
    return a;
}

__device__ __forceinline__ void cp16(uint32_t saddr, const void* gptr) {
    asm volatile("cp.async.cg.shared.global [%0], [%1], 16;"
                 :: "r"(saddr), "l"(gptr) : "memory");
}

__device__ __forceinline__ void mma_tf32(float c[4], const uint32_t a[4],
                                         uint32_t b0, uint32_t b1) {
    asm volatile(
        "mma.sync.aligned.m16n8k8.row.col.f32.tf32.tf32.f32 "
        "{%0,%1,%2,%3}, {%4,%5,%6,%7}, {%8,%9}, {%0,%1,%2,%3};\n"
        : "+f"(c[0]), "+f"(c[1]), "+f"(c[2]), "+f"(c[3])
        : "r"(a[0]), "r"(a[1]), "r"(a[2]), "r"(a[3]), "r"(b0), "r"(b1));
}

// ------------------------- GEMM ---------------------------------------------
// C[M,N] = A[M,K] @ Bt[N,K]^T (+bias). CTA tile 128x256, K-chunk 32,
// 256 threads = 8 warps in 2(M) x 4(N), warp tile 64x64.
// smem rows padded to 36 floats (144 B): conflict-free fragment reads.

#define ASTRIDE 36
#define A_FLOATS (128 * ASTRIDE)         // 4608
#define B_FLOATS (256 * ASTRIDE)         // 9216
#define SM_FLOATS (2 * A_FLOATS + 2 * B_FLOATS)   // 27648 floats = 110592 B

__global__ __launch_bounds__(256, 1)
void gemm_tf32(const float* __restrict__ A, const float* __restrict__ Bt,
               float* __restrict__ C, int K, int N,
               const float* __restrict__ bias)
{
    extern __shared__ float sm[];
    const uint32_t sbase = smem_u32(sm);

    const int t     = threadIdx.x;
    const int lane  = t & 31;
    const int warp  = t >> 5;
    const int warpM = warp >> 2;          // 0..1 -> rows [warpM*64, +64)
    const int warpN = warp & 3;           // 0..3 -> cols [warpN*64, +64)

    const size_t rowBase = (size_t)blockIdx.y * 128;
    const int    colBase = blockIdx.x * 256;
    const int NC = K >> 5;

    float acc[4][8][4];
    #pragma unroll
    for (int mt = 0; mt < 4; mt++)
        #pragma unroll
        for (int nt = 0; nt < 8; nt++)
            #pragma unroll
            for (int i = 0; i < 4; i++) acc[mt][nt][i] = 0.f;

    const float* Abase = A + rowBase * K;
    const float* Bbase = Bt + (size_t)colBase * K;

    // ---- async stage of one K-chunk into buffer `buf`
    auto stage = [&](int buf, int kc) {
        const uint32_t aOff = sbase + buf * (A_FLOATS * 4);
        const uint32_t bOff = sbase + (2 * A_FLOATS * 4) + buf * (B_FLOATS * 4);
        const float* Ap = Abase + kc * 32;
        const float* Bp = Bbase + kc * 32;
        #pragma unroll
        for (int it = 0; it < 4; it++) {          // A: 128 rows x 8 segs
            int seg = it * 256 + t;
            int r = seg >> 3, s = seg & 7;
            cp16(aOff + r * 144 + s * 16, Ap + (size_t)r * K + s * 4);
        }
        #pragma unroll
        for (int it = 0; it < 8; it++) {          // B: 256 rows x 8 segs
            int seg = it * 256 + t;
            int n = seg >> 3, s = seg & 7;
            cp16(bOff + n * 144 + s * 16, Bp + (size_t)n * K + s * 4);
        }
    };

    stage(0, 0);
    asm volatile("cp.async.commit_group;" ::: "memory");

    for (int kc = 0; kc < NC; kc++) {
        const int buf = kc & 1;
        if (kc + 1 < NC) {
            stage(buf ^ 1, kc + 1);
            asm volatile("cp.async.commit_group;" ::: "memory");
            asm volatile("cp.async.wait_group 1;" ::: "memory");
        } else {
            asm volatile("cp.async.wait_group 0;" ::: "memory");
        }
        __syncthreads();

        const float* abuf = sm + buf * A_FLOATS;
        const float* bbuf = sm + 2 * A_FLOATS + buf * B_FLOATS;

        #pragma unroll
        for (int ks = 0; ks < 4; ks++) {
            const int k0 = ks * 8;
            uint32_t a[4][4];
            #pragma unroll
            for (int mt = 0; mt < 4; mt++) {
                int r0 = warpM * 64 + mt * 16 + (lane >> 2);
                const float* ap = abuf + r0 * ASTRIDE + k0 + (lane & 3);
                a[mt][0] = f2tf32(ap[0]);
                a[mt][1] = f2tf32(ap[8 * ASTRIDE]);
                a[mt][2] = f2tf32(ap[4]);
                a[mt][3] = f2tf32(ap[8 * ASTRIDE + 4]);
            }
            #pragma unroll
            for (int nt = 0; nt < 8; nt++) {
                int c0 = warpN * 64 + nt * 8 + (lane >> 2);
                const float* bp = bbuf + c0 * ASTRIDE + k0 + (lane & 3);
                uint32_t b0 = f2tf32(bp[0]);
                uint32_t b1 = f2tf32(bp[4]);
                #pragma unroll
                for (int mt = 0; mt < 4; mt++)
                    mma_tf32(acc[mt][nt], a[mt], b0, b1);
            }
        }
        __syncthreads();   // all reads of `buf` done before restaging it
    }

    // ---- epilogue
    #pragma unroll
    for (int mt = 0; mt < 4; mt++) {
        size_t row = rowBase + warpM * 64 + mt * 16 + (lane >> 2);
        #pragma unroll
        for (int nt = 0; nt < 8; nt++) {
            int col = colBase + warpN * 64 + nt * 8 + 2 * (lane & 3);
            float b0 = 0.f, b1 = 0.f;
            if (bias) { b0 = bias[col]; b1 = bias[col + 1]; }
            *(float2*)(C + row * N + col) =
                make_float2(acc[mt][nt][0] + b0, acc[mt][nt][1] + b1);
            *(float2*)(C + (row + 8) * N + col) =
                make_float2(acc[mt][nt][2] + b0, acc[mt][nt][3] + b1);
        }
    }
}

// ------------------------- weight transpose ---------------------------------

__global__ void transpose_rc(const float* __restrict__ in, float* __restrict__ out,
                             int R, int C)
{
    __shared__ float tile[32][33];
    int c0 = blockIdx.x * 32, r0 = blockIdx.y * 32;
    #pragma unroll
    for (int i = threadIdx.y; i < 32; i += 8)
        tile[i][threadIdx.x] = in[(size_t)(r0 + i) * C + c0 + threadIdx.x];
    __syncthreads();
    #pragma unroll
    for (int i = threadIdx.y; i < 32; i += 8)
        out[(size_t)(c0 + i) * R + r0 + threadIdx.x] = tile[threadIdx.x][i];
}

// ------------------------- K2: attention core -------------------------------

__global__ __launch_bounds__(128)
void attn_core(const float* __restrict__ qkv, float* __restrict__ o)
{
    __shared__ float Qs[32][68];
    __shared__ float Ks[32][68];
    __shared__ float Vs[32][72];
    __shared__ float S [32][36];

    const int t    = threadIdx.x;
    const int lane = t & 31;
    const int warp = t >> 5;
    const int g    = blockIdx.x;
    const int h    = g & 7;
    const long tokBase = (long)(g >> 3) * 32;

    const float* base = qkv + tokBase * NQKV;

    #pragma unroll
    for (int i = 0; i < 4; i++) {
        int idx = i * 128 + t;
        int r  = idx >> 4;
        int cc = (idx & 15) * 4;
        const float* rowp = base + (long)r * NQKV + h * DH + cc;
        float4 q = *(const float4*)(rowp);
        float4 k = *(const float4*)(rowp + 512);
        float4 v = *(const float4*)(rowp + 1024);
        Qs[r][cc+0]=f2tf32f(q.x); Qs[r][cc+1]=f2tf32f(q.y);
        Qs[r][cc+2]=f2tf32f(q.z); Qs[r][cc+3]=f2tf32f(q.w);
        Ks[r][cc+0]=f2tf32f(k.x); Ks[r][cc+1]=f2tf32f(k.y);
        Ks[r][cc+2]=f2tf32f(k.z); Ks[r][cc+3]=f2tf32f(k.w);
        Vs[r][cc+0]=f2tf32f(v.x); Vs[r][cc+1]=f2tf32f(v.y);
        Vs[r][cc+2]=f2tf32f(v.z); Vs[r][cc+3]=f2tf32f(v.w);
    }
    __syncthreads();

    // S = Q K^T
    const int mt  = warp & 1;
    const int ntb = (warp >> 1) * 2;
    float sacc[2][4] = {{0.f,0.f,0.f,0.f},{0.f,0.f,0.f,0.f}};
    #pragma unroll
    for (int ks = 0; ks < 8; ks++) {
        int k0 = ks * 8;
        int r0 = mt * 16 + (lane >> 2);
        uint32_t a[4];
        a[0] = __float_as_uint(Qs[r0    ][k0     + (lane & 3)]);
        a[1] = __float_as_uint(Qs[r0 + 8][k0     + (lane & 3)]);
        a[2] = __float_as_uint(Qs[r0    ][k0 + 4 + (lane & 3)]);
        a[3] = __float_as_uint(Qs[r0 + 8][k0 + 4 + (lane & 3)]);
        #pragma unroll
        for (int n = 0; n < 2; n++) {
            int c0 = (ntb + n) * 8 + (lane >> 2);
            uint32_t b0 = __float_as_uint(Ks[c0][k0     + (lane & 3)]);
            uint32_t b1 = __float_as_uint(Ks[c0][k0 + 4 + (lane & 3)]);
            mma_tf32(sacc[n], a, b0, b1);
        }
    }
    #pragma unroll
    for (int n = 0; n < 2; n++) {
        int row = mt * 16 + (lane >> 2);
        int col = (ntb + n) * 8 + 2 * (lane & 3);
        S[row    ][col    ] = sacc[n][0] * ATT_SCALE;
        S[row    ][col + 1] = sacc[n][1] * ATT_SCALE;
        S[row + 8][col    ] = sacc[n][2] * ATT_SCALE;
        S[row + 8][col + 1] = sacc[n][3] * ATT_SCALE;
    }
    __syncthreads();

    // softmax: warp w -> rows 8w..8w+7, lane = column
    #pragma unroll
    for (int rr = 0; rr < 8; rr++) {
        int row = warp * 8 + rr;
        float v = S[row][lane];
        float m = v;
        #pragma unroll
        for (int off = 16; off; off >>= 1) m = fmaxf(m, __shfl_xor_sync(~0u, m, off));
        float e = __expf(v - m);
        float s = e;
        #pragma unroll
        for (int off = 16; off; off >>= 1) s += __shfl_xor_sync(~0u, s, off);
        S[row][lane] = e / s;
    }
    __syncthreads();

    // O = P V
    const int nt4 = (warp >> 1) * 4;
    float oacc[4][4];
    #pragma unroll
    for (int n = 0; n < 4; n++)
        #pragma unroll
        for (int i = 0; i < 4; i++) oacc[n][i] = 0.f;

    #pragma unroll
    for (int ks = 0; ks < 4; ks++) {
        int k0 = ks * 8;
        int r0 = mt * 16 + (lane >> 2);
        uint32_t a[4];
        a[0] = f2tf32(S[r0    ][k0     + (lane & 3)]);
        a[1] = f2tf32(S[r0 + 8][k0     + (lane & 3)]);
        a[2] = f2tf32(S[r0    ][k0 + 4 + (lane & 3)]);
        a[3] = f2tf32(S[r0 + 8][k0 + 4 + (lane & 3)]);
        #pragma unroll
        for (int n = 0; n < 4; n++) {
            int c0 = (nt4 + n) * 8 + (lane >> 2);
            uint32_t b0 = __float_as_uint(Vs[k0     + (lane & 3)][c0]);
            uint32_t b1 = __float_as_uint(Vs[k0 + 4 + (lane & 3)][c0]);
            mma_tf32(oacc[n], a, b0, b1);
        }
    }

    float* obase = o + tokBase * INNER + h * DH;
    #pragma unroll
    for (int n = 0; n < 4; n++) {
        int row = mt * 16 + (lane >> 2);
        int col = (nt4 + n) * 8 + 2 * (lane & 3);
        *(float2*)(obase + (long)row * INNER + col) =
            make_float2(oacc[n][0], oacc[n][1]);
        *(float2*)(obase + (long)(row + 8) * INNER + col) =
            make_float2(oacc[n][2], oacc[n][3]);
    }
}

// ------------------------- launch -------------------------------------------

extern "C" void kernel_launch(void* const* d_in, const int* in_sizes, int n_in,
                              void* d_out, int out_size)
{
    const float* x     = (const float*)d_in[0];
    const float* W_qkv = (const float*)d_in[1];
    const float* W_out = (const float*)d_in[2];
    const float* b_out = (const float*)d_in[3];
    float* out = (float*)d_out;

    float *qkv, *att, *wqT, *woT;
    cudaGetSymbolAddress((void**)&qkv, g_qkv);
    cudaGetSymbolAddress((void**)&att, g_attn);
    cudaGetSymbolAddress((void**)&wqT, g_WqkvT);
    cudaGetSymbolAddress((void**)&woT, g_WoutT);

    cudaFuncSetAttribute(gemm_tf32, cudaFuncAttributeMaxDynamicSharedMemorySize,
                         SM_FLOATS * 4);

    // W_qkv [256,1536] -> [1536,256]; W_out [512,256] -> [256,512]
    transpose_rc<<<dim3(NQKV / 32, DIMX / 32), dim3(32, 8)>>>(W_qkv, wqT, DIMX, NQKV);
    transpose_rc<<<dim3(DIMX / 32, INNER / 32), dim3(32, 8)>>>(W_out, woT, INNER, DIMX);

    // K1: qkv = x @ W_qkv  (M=131072, K=256, N=1536)
    gemm_tf32<<<dim3(NQKV / 256, TOKENS / 128), 256, SM_FLOATS * 4>>>(
        x, wqT, qkv, DIMX, NQKV, nullptr);

    // K2: attention
    attn_core<<<GROUPS * HEADS, 128>>>(qkv, att);

    // K3: out = att @ W_out + b  (M=131072, K=512, N=256)
    gemm_tf32<<<dim3(DIMX / 256, TOKENS / 128), 256, SM_FLOATS * 4>>>(
        att, woT, out, INNER, DIMX, b_out);
}

// round 5
// speedup vs baseline: 1.0528x; 1.0528x over previous
#include <cuda_runtime.h>
#include <cstdint>
#include <math.h>

// ---------------------------------------------------------------------------
// Attention_37074157699274 — round 5: mma.sync tf32 GEMM, 64x64 warp tiles,
// register-prefetch double-buffered staging, cvt at staging (pure-LDS consume).
//   T1/T2: transpose weights -> [N,K] scratch
//   K1: qkv  = x @ W_qkv      tile 128x256, K=256
//   K2: attn per (b,p,h)      (unchanged, proven)
//   K3: out  = attn @ W_out+b tile 128x256, K=512
// ---------------------------------------------------------------------------

#define TOKENS   131072
#define GROUPS   4096
#define DIMX     256
#define NQKV     1536
#define INNER    512
#define HEADS    8
#define DH       64
#define ATT_SCALE 0.125f

__device__ float g_qkv [(size_t)TOKENS * NQKV];    // 805 MB
__device__ float g_attn[(size_t)TOKENS * INNER];   // 268 MB
__device__ float g_WqkvT[(size_t)NQKV * DIMX];
__device__ float g_WoutT[(size_t)DIMX * INNER];

// ------------------------- helpers ------------------------------------------

__device__ __forceinline__ uint32_t f2tf32(float x) {
    uint32_t u;
    asm("cvt.rna.tf32.f32 %0, %1;" : "=r"(u) : "f"(x));
    return u;
}
__device__ __forceinline__ float f2tf32f(float x) { return __uint_as_float(f2tf32(x)); }

__device__ __forceinline__ void mma_tf32(float c[4], const uint32_t a[4],
                                         uint32_t b0, uint32_t b1) {
    asm volatile(
        "mma.sync.aligned.m16n8k8.row.col.f32.tf32.tf32.f32 "
        "{%0,%1,%2,%3}, {%4,%5,%6,%7}, {%8,%9}, {%0,%1,%2,%3};\n"
        : "+f"(c[0]), "+f"(c[1]), "+f"(c[2]), "+f"(c[3])
        : "r"(a[0]), "r"(a[1]), "r"(a[2]), "r"(a[3]), "r"(b0), "r"(b1));
}

// ------------------------- GEMM ---------------------------------------------
// C[M,N] = A[M,K] @ Bt[N,K]^T (+bias). CTA tile 128x256, K-chunk 32,
// 256 threads = 8 warps in 2(M) x 4(N), warp tile 64x64.
// Staging: LDG chunk k+2 into regs during compute of chunk k; STS (with
// tf32 cvt) into the spare buffer right after the per-chunk barrier.
// Consume path is pure LDS (conflict-free, rows padded to 36 floats).

#define ASTRIDE 36
#define A_FLOATS (128 * ASTRIDE)         // 4608
#define B_FLOATS (256 * ASTRIDE)         // 9216
#define SM_FLOATS (2 * (A_FLOATS + B_FLOATS))     // 27648 floats = 110592 B

__global__ __launch_bounds__(256, 1)
void gemm_tf32(const float* __restrict__ A, const float* __restrict__ Bt,
               float* __restrict__ C, int K, int N,
               const float* __restrict__ bias)
{
    extern __shared__ float sm[];
    // buffer b: A at sm + b*(A_FLOATS+B_FLOATS), B right after A
    const int t     = threadIdx.x;
    const int lane  = t & 31;
    const int warp  = t >> 5;
    const int warpM = warp >> 2;          // 0..1 -> rows [warpM*64, +64)
    const int warpN = warp & 3;           // 0..3 -> cols [warpN*64, +64)

    const size_t rowBase = (size_t)blockIdx.y * 128;
    const int    colBase = blockIdx.x * 256;
    const int NC = K >> 5;

    float acc[4][8][4];
    #pragma unroll
    for (int mt = 0; mt < 4; mt++)
        #pragma unroll
        for (int nt = 0; nt < 8; nt++)
            #pragma unroll
            for (int i = 0; i < 4; i++) acc[mt][nt][i] = 0.f;

    const float* Abase = A + rowBase * K;
    const float* Bbase = Bt + (size_t)colBase * K;

    // per-thread staging coordinates (fixed)
    int aR[4], aS[4], bR[8], bS[8];
    #pragma unroll
    for (int it = 0; it < 4; it++) {
        int seg = it * 256 + t;
        aR[it] = seg >> 3; aS[it] = (seg & 7) * 4;
    }
    #pragma unroll
    for (int it = 0; it < 8; it++) {
        int seg = it * 256 + t;
        bR[it] = seg >> 3; bS[it] = (seg & 7) * 4;
    }

    float4 pa[4], pb[8];

    auto ldg = [&](int kc) {
        const float* Ap = Abase + kc * 32;
        const float* Bp = Bbase + kc * 32;
        #pragma unroll
        for (int it = 0; it < 4; it++)
            pa[it] = *(const float4*)(Ap + (size_t)aR[it] * K + aS[it]);
        #pragma unroll
        for (int it = 0; it < 8; it++)
            pb[it] = *(const float4*)(Bp + (size_t)bR[it] * K + bS[it]);
    };
    auto sts = [&](int buf) {
        float* ab = sm + buf * (A_FLOATS + B_FLOATS);
        float* bb = ab + A_FLOATS;
        #pragma unroll
        for (int it = 0; it < 4; it++) {
            float* p = ab + aR[it] * ASTRIDE + aS[it];
            p[0] = f2tf32f(pa[it].x); p[1] = f2tf32f(pa[it].y);
            p[2] = f2tf32f(pa[it].z); p[3] = f2tf32f(pa[it].w);
        }
        #pragma unroll
        for (int it = 0; it < 8; it++) {
            float* p = bb + bR[it] * ASTRIDE + bS[it];
            p[0] = f2tf32f(pb[it].x); p[1] = f2tf32f(pb[it].y);
            p[2] = f2tf32f(pb[it].z); p[3] = f2tf32f(pb[it].w);
        }
    };

    // prologue
    ldg(0);
    sts(0);
    if (NC > 1) ldg(1);

    for (int kc = 0; kc < NC; kc++) {
        __syncthreads();                 // buf[kc&1] ready; buf[(kc+1)&1] free
        if (kc + 1 < NC) sts((kc + 1) & 1);
        if (kc + 2 < NC) ldg(kc + 2);

        const float* abuf = sm + (kc & 1) * (A_FLOATS + B_FLOATS);
        const float* bbuf = abuf + A_FLOATS;

        #pragma unroll
        for (int ks = 0; ks < 4; ks++) {
            const int k0 = ks * 8;
            uint32_t a[4][4];
            #pragma unroll
            for (int mt = 0; mt < 4; mt++) {
                int r0 = warpM * 64 + mt * 16 + (lane >> 2);
                const float* ap = abuf + r0 * ASTRIDE + k0 + (lane & 3);
                a[mt][0] = __float_as_uint(ap[0]);
                a[mt][1] = __float_as_uint(ap[8 * ASTRIDE]);
                a[mt][2] = __float_as_uint(ap[4]);
                a[mt][3] = __float_as_uint(ap[8 * ASTRIDE + 4]);
            }
            #pragma unroll
            for (int nt = 0; nt < 8; nt++) {
                int c0 = warpN * 64 + nt * 8 + (lane >> 2);
                const float* bp = bbuf + c0 * ASTRIDE + k0 + (lane & 3);
                uint32_t b0 = __float_as_uint(bp[0]);
                uint32_t b1 = __float_as_uint(bp[4]);
                #pragma unroll
                for (int mt = 0; mt < 4; mt++)
                    mma_tf32(acc[mt][nt], a[mt], b0, b1);
            }
        }
    }

    // ---- epilogue
    #pragma unroll
    for (int mt = 0; mt < 4; mt++) {
        size_t row = rowBase + warpM * 64 + mt * 16 + (lane >> 2);
        #pragma unroll
        for (int nt = 0; nt < 8; nt++) {
            int col = colBase + warpN * 64 + nt * 8 + 2 * (lane & 3);
            float b0 = 0.f, b1 = 0.f;
            if (bias) { b0 = bias[col]; b1 = bias[col + 1]; }
            *(float2*)(C + row * N + col) =
                make_float2(acc[mt][nt][0] + b0, acc[mt][nt][1] + b1);
            *(float2*)(C + (row + 8) * N + col) =
                make_float2(acc[mt][nt][2] + b0, acc[mt][nt][3] + b1);
        }
    }
}

// ------------------------- weight transpose ---------------------------------

__global__ void transpose_rc(const float* __restrict__ in, float* __restrict__ out,
                             int R, int C)
{
    __shared__ float tile[32][33];
    int c0 = blockIdx.x * 32, r0 = blockIdx.y * 32;
    #pragma unroll
    for (int i = threadIdx.y; i < 32; i += 8)
        tile[i][threadIdx.x] = in[(size_t)(r0 + i) * C + c0 + threadIdx.x];
    __syncthreads();
    #pragma unroll
    for (int i = threadIdx.y; i < 32; i += 8)
        out[(size_t)(c0 + i) * R + r0 + threadIdx.x] = tile[threadIdx.x][i];
}

// ------------------------- K2: attention core -------------------------------

__global__ __launch_bounds__(128)
void attn_core(const float* __restrict__ qkv, float* __restrict__ o)
{
    __shared__ float Qs[32][68];
    __shared__ float Ks[32][68];
    __shared__ float Vs[32][72];
    __shared__ float S [32][36];

    const int t    = threadIdx.x;
    const int lane = t & 31;
    const int warp = t >> 5;
    const int g    = blockIdx.x;
    const int h    = g & 7;
    const long tokBase = (long)(g >> 3) * 32;

    const float* base = qkv + tokBase * NQKV;

    #pragma unroll
    for (int i = 0; i < 4; i++) {
        int idx = i * 128 + t;
        int r  = idx >> 4;
        int cc = (idx & 15) * 4;
        const float* rowp = base + (long)r * NQKV + h * DH + cc;
        float4 q = *(const float4*)(rowp);
        float4 k = *(const float4*)(rowp + 512);
        float4 v = *(const float4*)(rowp + 1024);
        Qs[r][cc+0]=f2tf32f(q.x); Qs[r][cc+1]=f2tf32f(q.y);
        Qs[r][cc+2]=f2tf32f(q.z); Qs[r][cc+3]=f2tf32f(q.w);
        Ks[r][cc+0]=f2tf32f(k.x); Ks[r][cc+1]=f2tf32f(k.y);
        Ks[r][cc+2]=f2tf32f(k.z); Ks[r][cc+3]=f2tf32f(k.w);
        Vs[r][cc+0]=f2tf32f(v.x); Vs[r][cc+1]=f2tf32f(v.y);
        Vs[r][cc+2]=f2tf32f(v.z); Vs[r][cc+3]=f2tf32f(v.w);
    }
    __syncthreads();

    // S = Q K^T
    const int mt  = warp & 1;
    const int ntb = (warp >> 1) * 2;
    float sacc[2][4] = {{0.f,0.f,0.f,0.f},{0.f,0.f,0.f,0.f}};
    #pragma unroll
    for (int ks = 0; ks < 8; ks++) {
        int k0 = ks * 8;
        int r0 = mt * 16 + (lane >> 2);
        uint32_t a[4];
        a[0] = __float_as_uint(Qs[r0    ][k0     + (lane & 3)]);
        a[1] = __float_as_uint(Qs[r0 + 8][k0     + (lane & 3)]);
        a[2] = __float_as_uint(Qs[r0    ][k0 + 4 + (lane & 3)]);
        a[3] = __float_as_uint(Qs[r0 + 8][k0 + 4 + (lane & 3)]);
        #pragma unroll
        for (int n = 0; n < 2; n++) {
            int c0 = (ntb + n) * 8 + (lane >> 2);
            uint32_t b0 = __float_as_uint(Ks[c0][k0     + (lane & 3)]);
            uint32_t b1 = __float_as_uint(Ks[c0][k0 + 4 + (lane & 3)]);
            mma_tf32(sacc[n], a, b0, b1);
        }
    }
    #pragma unroll
    for (int n = 0; n < 2; n++) {
        int row = mt * 16 + (lane >> 2);
        int col = (ntb + n) * 8 + 2 * (lane & 3);
        S[row    ][col    ] = sacc[n][0] * ATT_SCALE;
        S[row    ][col + 1] = sacc[n][1] * ATT_SCALE;
        S[row + 8][col    ] = sacc[n][2] * ATT_SCALE;
        S[row + 8][col + 1] = sacc[n][3] * ATT_SCALE;
    }
    __syncthreads();

    // softmax: warp w -> rows 8w..8w+7, lane = column
    #pragma unroll
    for (int rr = 0; rr < 8; rr++) {
        int row = warp * 8 + rr;
        float v = S[row][lane];
        float m = v;
        #pragma unroll
        for (int off = 16; off; off >>= 1) m = fmaxf(m, __shfl_xor_sync(~0u, m, off));
        float e = __expf(v - m);
        float s = e;
        #pragma unroll
        for (int off = 16; off; off >>= 1) s += __shfl_xor_sync(~0u, s, off);
        S[row][lane] = e / s;
    }
    __syncthreads();

    // O = P V
    const int nt4 = (warp >> 1) * 4;
    float oacc[4][4];
    #pragma unroll
    for (int n = 0; n < 4; n++)
        #pragma unroll
        for (int i = 0; i < 4; i++) oacc[n][i] = 0.f;

    #pragma unroll
    for (int ks = 0; ks < 4; ks++) {
        int k0 = ks * 8;
        int r0 = mt * 16 + (lane >> 2);
        uint32_t a[4];
        a[0] = f2tf32(S[r0    ][k0     + (lane & 3)]);
        a[1] = f2tf32(S[r0 + 8][k0     + (lane & 3)]);
        a[2] = f2tf32(S[r0    ][k0 + 4 + (lane & 3)]);
        a[3] = f2tf32(S[r0 + 8][k0 + 4 + (lane & 3)]);
        #pragma unroll
        for (int n = 0; n < 4; n++) {
            int c0 = (nt4 + n) * 8 + (lane >> 2);
            uint32_t b0 = __float_as_uint(Vs[k0     + (lane & 3)][c0]);
            uint32_t b1 = __float_as_uint(Vs[k0 + 4 + (lane & 3)][c0]);
            mma_tf32(oacc[n], a, b0, b1);
        }
    }

    float* obase = o + tokBase * INNER + h * DH;
    #pragma unroll
    for (int n = 0; n < 4; n++) {
        int row = mt * 16 + (lane >> 2);
        int col = (nt4 + n) * 8 + 2 * (lane & 3);
        *(float2*)(obase + (long)row * INNER + col) =
            make_float2(oacc[n][0], oacc[n][1]);
        *(float2*)(obase + (long)(row + 8) * INNER + col) =
            make_float2(oacc[n][2], oacc[n][3]);
    }
}

// ------------------------- launch -------------------------------------------

extern "C" void kernel_launch(void* const* d_in, const int* in_sizes, int n_in,
                              void* d_out, int out_size)
{
    const float* x     = (const float*)d_in[0];
    const float* W_qkv = (const float*)d_in[1];
    const float* W_out = (const float*)d_in[2];
    const float* b_out = (const float*)d_in[3];
    float* out = (float*)d_out;

    float *qkv, *att, *wqT, *woT;
    cudaGetSymbolAddress((void**)&qkv, g_qkv);
    cudaGetSymbolAddress((void**)&att, g_attn);
    cudaGetSymbolAddress((void**)&wqT, g_WqkvT);
    cudaGetSymbolAddress((void**)&woT, g_WoutT);

    cudaFuncSetAttribute(gemm_tf32, cudaFuncAttributeMaxDynamicSharedMemorySize,
                         SM_FLOATS * 4);

    // W_qkv [256,1536] -> [1536,256]; W_out [512,256] -> [256,512]
    transpose_rc<<<dim3(NQKV / 32, DIMX / 32), dim3(32, 8)>>>(W_qkv, wqT, DIMX, NQKV);
    transpose_rc<<<dim3(DIMX / 32, INNER / 32), dim3(32, 8)>>>(W_out, woT, INNER, DIMX);

    // K1: qkv = x @ W_qkv  (M=131072, K=256, N=1536)
    gemm_tf32<<<dim3(NQKV / 256, TOKENS / 128), 256, SM_FLOATS * 4>>>(
        x, wqT, qkv, DIMX, NQKV, nullptr);

    // K2: attention
    attn_core<<<GROUPS * HEADS, 128>>>(qkv, att);

    // K3: out = att @ W_out + b  (M=131072, K=512, N=256)
    gemm_tf32<<<dim3(DIMX / 256, TOKENS / 128), 256, SM_FLOATS * 4>>>(
        att, woT, out, INNER, DIMX, b_out);
}

// round 6
// speedup vs baseline: 1.3130x; 1.2471x over previous
#include <cuda_runtime.h>
#include <cuda_fp16.h>
#include <cstdint>
#include <math.h>

// ---------------------------------------------------------------------------
// Attention_37074157699274 — round 6: fp16 mma.sync (m16n8k16) everywhere.
// fp16 mantissa == tf32 mantissa (10 bits) -> same accuracy, 2x tensor rate,
// and fp16 scratch halves the DRAM traffic that bounds attn_core.
//   T1/T2: transpose weights -> [N,K] fp16 scratch
//   K1: qkv  = x @ W_qkv      tile 128x256, half out
//   K2: attn per (b,p,h)      fp16 tiles, fp32 softmax
//   K3: out  = attn @ W_out+b half A, fp32 out
// ---------------------------------------------------------------------------

#define TOKENS   131072
#define GROUPS   4096
#define DIMX     256
#define NQKV     1536
#define INNER    512
#define HEADS    8
#define DH       64
#define ATT_SCALE 0.125f

__device__ __half g_qkv [(size_t)TOKENS * NQKV];    // 403 MB
__device__ __half g_attn[(size_t)TOKENS * INNER];   // 134 MB
__device__ __half g_WqkvT[(size_t)NQKV * DIMX];
__device__ __half g_WoutT[(size_t)DIMX * INNER];

// ------------------------- helpers ------------------------------------------

__device__ __forceinline__ uint32_t pack2h(float x, float y) {
    __half2 h = __halves2half2(__float2half_rn(x), __float2half_rn(y));
    return *reinterpret_cast<uint32_t*>(&h);
}

__device__ __forceinline__ void mma_f16(float c[4], uint32_t a0, uint32_t a1,
                                        uint32_t a2, uint32_t a3,
                                        uint32_t b0, uint32_t b1) {
    asm volatile(
        "mma.sync.aligned.m16n8k16.row.col.f32.f16.f16.f32 "
        "{%0,%1,%2,%3}, {%4,%5,%6,%7}, {%8,%9}, {%0,%1,%2,%3};\n"
        : "+f"(c[0]), "+f"(c[1]), "+f"(c[2]), "+f"(c[3])
        : "r"(a0), "r"(a1), "r"(a2), "r"(a3), "r"(b0), "r"(b1));
}

// ------------------------- GEMM ---------------------------------------------
// C[M,N] = A[M,K] @ Bt[N,K]^T (+bias). CTA tile 128x256, K-chunk 32,
// 8 warps in 2(M) x 4(N), warp tile 64x64. fp16 operands in smem
// (rows padded to 40 halfs = conflict-free fragment loads), fp32 acc.
// Register-prefetch double buffering (LDG k+2 during compute of k).

#define STR   40                       // halfs per smem row
#define A_H   (128 * STR)              // 5120 halfs
#define B_H   (256 * STR)              // 10240 halfs
#define BUF_H (A_H + B_H)              // per-buffer halfs
#define SM_BYTES (2 * BUF_H * 2)       // 61440 B

template<typename TA, typename TC>
__global__ __launch_bounds__(256, 1)
void gemm_h(const TA* __restrict__ A, const __half* __restrict__ Bt,
            TC* __restrict__ C, int K, int N, const float* __restrict__ bias)
{
    extern __shared__ __half sh[];

    const int t     = threadIdx.x;
    const int lane  = t & 31;
    const int warp  = t >> 5;
    const int warpM = warp >> 2;        // 0..1
    const int warpN = warp & 3;         // 0..3

    const size_t rowBase = (size_t)blockIdx.y * 128;
    const int    colBase = blockIdx.x * 256;
    const int NC = K >> 5;

    float acc[4][8][4];
    #pragma unroll
    for (int mt = 0; mt < 4; mt++)
        #pragma unroll
        for (int nt = 0; nt < 8; nt++)
            #pragma unroll
            for (int i = 0; i < 4; i++) acc[mt][nt][i] = 0.f;

    const TA*     Abase = A  + rowBase * K;
    const __half* Bbase = Bt + (size_t)colBase * K;

    // fixed per-thread staging coords: seg = 4 consecutive k-elements
    int aR[4], aS[4], bR[8], bS[8];
    #pragma unroll
    for (int it = 0; it < 4; it++) {
        int seg = it * 256 + t;
        aR[it] = seg >> 3; aS[it] = (seg & 7) * 4;
    }
    #pragma unroll
    for (int it = 0; it < 8; it++) {
        int seg = it * 256 + t;
        bR[it] = seg >> 3; bS[it] = (seg & 7) * 4;
    }

    uint2 pa[4], pb[8];

    auto ldg = [&](int kc) {
        const __half* Bp = Bbase + kc * 32;
        #pragma unroll
        for (int it = 0; it < 4; it++) {
            if constexpr (sizeof(TA) == 4) {
                const float* Ap = (const float*)Abase + kc * 32;
                float4 v = *(const float4*)(Ap + (size_t)aR[it] * K + aS[it]);
                pa[it] = make_uint2(pack2h(v.x, v.y), pack2h(v.z, v.w));
            } else {
                const __half* Ap = (const __half*)Abase + kc * 32;
                pa[it] = *(const uint2*)(Ap + (size_t)aR[it] * K + aS[it]);
            }
        }
        #pragma unroll
        for (int it = 0; it < 8; it++)
            pb[it] = *(const uint2*)(Bp + (size_t)bR[it] * K + bS[it]);
    };
    auto sts = [&](int buf) {
        __half* ab = sh + buf * BUF_H;
        __half* bb = ab + A_H;
        #pragma unroll
        for (int it = 0; it < 4; it++)
            *(uint2*)(ab + aR[it] * STR + aS[it]) = pa[it];
        #pragma unroll
        for (int it = 0; it < 8; it++)
            *(uint2*)(bb + bR[it] * STR + bS[it]) = pb[it];
    };

    ldg(0);
    sts(0);
    if (NC > 1) ldg(1);

    for (int kc = 0; kc < NC; kc++) {
        __syncthreads();
        if (kc + 1 < NC) sts((kc + 1) & 1);
        if (kc + 2 < NC) ldg(kc + 2);

        const __half* abuf = sh + (kc & 1) * BUF_H;
        const __half* bbuf = abuf + A_H;

        #pragma unroll
        for (int ks = 0; ks < 2; ks++) {          // two k16 steps per chunk
            const int k0 = ks * 16;
            uint32_t a[4][4];
            #pragma unroll
            for (int mt = 0; mt < 4; mt++) {
                int r0 = warpM * 64 + mt * 16 + (lane >> 2);
                const __half* ap = abuf + r0 * STR + k0 + (lane & 3) * 2;
                a[mt][0] = *(const uint32_t*)(ap);
                a[mt][1] = *(const uint32_t*)(ap + 8 * STR);
                a[mt][2] = *(const uint32_t*)(ap + 8);
                a[mt][3] = *(const uint32_t*)(ap + 8 * STR + 8);
            }
            #pragma unroll
            for (int nt = 0; nt < 8; nt++) {
                int c0 = warpN * 64 + nt * 8 + (lane >> 2);
                const __half* bp = bbuf + c0 * STR + k0 + (lane & 3) * 2;
                uint32_t b0 = *(const uint32_t*)(bp);
                uint32_t b1 = *(const uint32_t*)(bp + 8);
                #pragma unroll
                for (int mt = 0; mt < 4; mt++)
                    mma_f16(acc[mt][nt], a[mt][0], a[mt][1], a[mt][2], a[mt][3],
                            b0, b1);
            }
        }
    }

    // ---- epilogue
    #pragma unroll
    for (int mt = 0; mt < 4; mt++) {
        size_t row = rowBase + warpM * 64 + mt * 16 + (lane >> 2);
        #pragma unroll
        for (int nt = 0; nt < 8; nt++) {
            int col = colBase + warpN * 64 + nt * 8 + 2 * (lane & 3);
            if constexpr (sizeof(TC) == 2) {
                __half* cp = (__half*)C;
                *(uint32_t*)(cp + row * N + col) =
                    pack2h(acc[mt][nt][0], acc[mt][nt][1]);
                *(uint32_t*)(cp + (row + 8) * N + col) =
                    pack2h(acc[mt][nt][2], acc[mt][nt][3]);
            } else {
                float b0 = 0.f, b1 = 0.f;
                if (bias) { b0 = bias[col]; b1 = bias[col + 1]; }
                float* cp = (float*)C;
                *(float2*)(cp + row * N + col) =
                    make_float2(acc[mt][nt][0] + b0, acc[mt][nt][1] + b1);
                *(float2*)(cp + (row + 8) * N + col) =
                    make_float2(acc[mt][nt][2] + b0, acc[mt][nt][3] + b1);
            }
        }
    }
}

// ------------------------- weight transpose (fp32 -> fp16) ------------------

__global__ void transpose_h(const float* __restrict__ in, __half* __restrict__ out,
                            int R, int C)
{
    __shared__ float tile[32][33];
    int c0 = blockIdx.x * 32, r0 = blockIdx.y * 32;
    #pragma unroll
    for (int i = threadIdx.y; i < 32; i += 8)
        tile[i][threadIdx.x] = in[(size_t)(r0 + i) * C + c0 + threadIdx.x];
    __syncthreads();
    #pragma unroll
    for (int i = threadIdx.y; i < 32; i += 8)
        out[(size_t)(c0 + i) * R + r0 + threadIdx.x] =
            __float2half_rn(tile[threadIdx.x][i]);
}

// ------------------------- K2: attention core (fp16) ------------------------
// One block per (group, head), 128 threads = 4 warps.
// Q/K smem rows padded to 72 halfs; V staged transposed (Vs[d][j], 40-half rows).

#define QSTR 72
#define VSTR 40

__global__ __launch_bounds__(128)
void attn_core(const __half* __restrict__ qkv, __half* __restrict__ o)
{
    __shared__ __half Qs[32 * QSTR];
    __shared__ __half Ks[32 * QSTR];
    __shared__ __half Vs[64 * VSTR];
    __shared__ float  S [32][36];

    const int t    = threadIdx.x;
    const int lane = t & 31;
    const int warp = t >> 5;
    const int g    = blockIdx.x;
    const int h    = g & 7;
    const size_t tokBase = (size_t)(g >> 3) * 32;

    const __half* base = qkv + tokBase * NQKV + h * DH;

    // load Q/K (direct) and V (transposed) tiles
    #pragma unroll
    for (int i = 0; i < 4; i++) {
        int idx = i * 128 + t;          // 0..511
        int r   = idx >> 4;             // token 0..31
        int seg = idx & 15;             // 4-half segment 0..15
        const __half* rp = base + (size_t)r * NQKV + seg * 4;
        uint2 q = *(const uint2*)(rp);
        uint2 k = *(const uint2*)(rp + 512);
        uint2 v = *(const uint2*)(rp + 1024);
        *(uint2*)(Qs + r * QSTR + seg * 4) = q;
        *(uint2*)(Ks + r * QSTR + seg * 4) = k;
        __half vh[4];
        *(uint2*)vh = v;
        #pragma unroll
        for (int j = 0; j < 4; j++)
            Vs[(seg * 4 + j) * VSTR + r] = vh[j];
    }
    __syncthreads();

    // ---- S = Q K^T (K=64 -> 4 k16 steps)
    const int mt  = warp & 1;
    const int ntb = (warp >> 1) * 2;
    float sacc[2][4] = {{0.f,0.f,0.f,0.f},{0.f,0.f,0.f,0.f}};
    #pragma unroll
    for (int ks = 0; ks < 4; ks++) {
        const int k0 = ks * 16;
        int r0 = mt * 16 + (lane >> 2);
        const __half* ap = Qs + r0 * QSTR + k0 + (lane & 3) * 2;
        uint32_t a0 = *(const uint32_t*)(ap);
        uint32_t a1 = *(const uint32_t*)(ap + 8 * QSTR);
        uint32_t a2 = *(const uint32_t*)(ap + 8);
        uint32_t a3 = *(const uint32_t*)(ap + 8 * QSTR + 8);
        #pragma unroll
        for (int n = 0; n < 2; n++) {
            int c0 = (ntb + n) * 8 + (lane >> 2);
            const __half* bp = Ks + c0 * QSTR + k0 + (lane & 3) * 2;
            uint32_t b0 = *(const uint32_t*)(bp);
            uint32_t b1 = *(const uint32_t*)(bp + 8);
            mma_f16(sacc[n], a0, a1, a2, a3, b0, b1);
        }
    }
    #pragma unroll
    for (int n = 0; n < 2; n++) {
        int row = mt * 16 + (lane >> 2);
        int col = (ntb + n) * 8 + 2 * (lane & 3);
        S[row    ][col    ] = sacc[n][0] * ATT_SCALE;
        S[row    ][col + 1] = sacc[n][1] * ATT_SCALE;
        S[row + 8][col    ] = sacc[n][2] * ATT_SCALE;
        S[row + 8][col + 1] = sacc[n][3] * ATT_SCALE;
    }
    __syncthreads();

    // ---- softmax: warp w -> rows 8w..8w+7, lane = column
    #pragma unroll
    for (int rr = 0; rr < 8; rr++) {
        int row = warp * 8 + rr;
        float v = S[row][lane];
        float m = v;
        #pragma unroll
        for (int off = 16; off; off >>= 1) m = fmaxf(m, __shfl_xor_sync(~0u, m, off));
        float e = __expf(v - m);
        float s = e;
        #pragma unroll
        for (int off = 16; off; off >>= 1) s += __shfl_xor_sync(~0u, s, off);
        S[row][lane] = e / s;
    }
    __syncthreads();

    // ---- O = P V (K=32 -> 2 k16 steps)
    const int nt4 = (warp >> 1) * 4;
    float oacc[4][4];
    #pragma unroll
    for (int n = 0; n < 4; n++)
        #pragma unroll
        for (int i = 0; i < 4; i++) oacc[n][i] = 0.f;

    #pragma unroll
    for (int ks = 0; ks < 2; ks++) {
        const int k0 = ks * 16;
        int r0 = mt * 16 + (lane >> 2);
        int c  = k0 + (lane & 3) * 2;
        uint32_t a0 = pack2h(S[r0    ][c    ], S[r0    ][c + 1]);
        uint32_t a1 = pack2h(S[r0 + 8][c    ], S[r0 + 8][c + 1]);
        uint32_t a2 = pack2h(S[r0    ][c + 8], S[r0    ][c + 9]);
        uint32_t a3 = pack2h(S[r0 + 8][c + 8], S[r0 + 8][c + 9]);
        #pragma unroll
        for (int n = 0; n < 4; n++) {
            int n0 = (nt4 + n) * 8 + (lane >> 2);
            const __half* bp = Vs + n0 * VSTR + k0 + (lane & 3) * 2;
            uint32_t b0 = *(const uint32_t*)(bp);
            uint32_t b1 = *(const uint32_t*)(bp + 8);
            mma_f16(oacc[n], a0, a1, a2, a3, b0, b1);
        }
    }

    __half* obase = o + tokBase * INNER + h * DH;
    #pragma unroll
    for (int n = 0; n < 4; n++) {
        int row = mt * 16 + (lane >> 2);
        int col = (nt4 + n) * 8 + 2 * (lane & 3);
        *(uint32_t*)(obase + (size_t)row * INNER + col) =
            pack2h(oacc[n][0], oacc[n][1]);
        *(uint32_t*)(obase + (size_t)(row + 8) * INNER + col) =
            pack2h(oacc[n][2], oacc[n][3]);
    }
}

// ------------------------- launch -------------------------------------------

extern "C" void kernel_launch(void* const* d_in, const int* in_sizes, int n_in,
                              void* d_out, int out_size)
{
    const float* x     = (const float*)d_in[0];
    const float* W_qkv = (const float*)d_in[1];
    const float* W_out = (const float*)d_in[2];
    const float* b_out = (const float*)d_in[3];
    float* out = (float*)d_out;

    __half *qkv, *att, *wqT, *woT;
    cudaGetSymbolAddress((void**)&qkv, g_qkv);
    cudaGetSymbolAddress((void**)&att, g_attn);
    cudaGetSymbolAddress((void**)&wqT, g_WqkvT);
    cudaGetSymbolAddress((void**)&woT, g_WoutT);

    cudaFuncSetAttribute(gemm_h<float, __half>,
                         cudaFuncAttributeMaxDynamicSharedMemorySize, SM_BYTES);
    cudaFuncSetAttribute(gemm_h<__half, float>,
                         cudaFuncAttributeMaxDynamicSharedMemorySize, SM_BYTES);

    // W_qkv [256,1536] -> [1536,256] fp16 ; W_out [512,256] -> [256,512] fp16
    transpose_h<<<dim3(NQKV / 32, DIMX / 32), dim3(32, 8)>>>(W_qkv, wqT, DIMX, NQKV);
    transpose_h<<<dim3(DIMX / 32, INNER / 32), dim3(32, 8)>>>(W_out, woT, INNER, DIMX);

    // K1: qkv = x @ W_qkv  (M=131072, K=256, N=1536), half output
    gemm_h<float, __half><<<dim3(NQKV / 256, TOKENS / 128), 256, SM_BYTES>>>(
        x, wqT, qkv, DIMX, NQKV, nullptr);

    // K2: attention
    attn_core<<<GROUPS * HEADS, 128>>>(qkv, att);

    // K3: out = att @ W_out + b  (M=131072, K=512, N=256), fp32 output
    gemm_h<__half, float><<<dim3(DIMX / 256, TOKENS / 128), 256, SM_BYTES>>>(
        att, woT, out, INNER, DIMX, b_out);
}

// round 7
// speedup vs baseline: 1.6071x; 1.2240x over previous
#include <cuda_runtime.h>
#include <cuda_fp16.h>
#include <cstdint>

// ---------------------------------------------------------------------------
// Attention_37074157699274 — round 7: fp16 mma.sync + ldmatrix fragments +
// 4-stage cp.async GEMM pipeline + fp16 x pre-convert.
//   K0: x -> fp16
//   T1/T2: weights -> [N,K] fp16
//   K1: qkv = xh @ W_qkv  (cp.async 4-stage, ldmatrix, tile 128x256)
//   K2: attn (ldmatrix Q/K, ldmatrix.trans V, fp32 softmax)
//   K3: out = attn @ W_out + b
// ---------------------------------------------------------------------------

#define TOKENS   131072
#define GROUPS   4096
#define DIMX     256
#define NQKV     1536
#define INNER    512
#define HEADS    8
#define DH       64
#define ATT_SCALE 0.125f

__device__ __half g_xh  [(size_t)TOKENS * DIMX];    // 67 MB
__device__ __half g_qkv [(size_t)TOKENS * NQKV];    // 403 MB
__device__ __half g_attn[(size_t)TOKENS * INNER];   // 134 MB
__device__ __half g_WqkvT[(size_t)NQKV * DIMX];
__device__ __half g_WoutT[(size_t)DIMX * INNER];

// ------------------------- helpers ------------------------------------------

__device__ __forceinline__ uint32_t pack2h(float x, float y) {
    __half2 h = __halves2half2(__float2half_rn(x), __float2half_rn(y));
    return *reinterpret_cast<uint32_t*>(&h);
}
__device__ __forceinline__ uint32_t smem_u32(const void* p) {
    uint32_t a;
    asm("{ .reg .u64 t; cvta.to.shared.u64 t, %1; cvt.u32.u64 %0, t; }"
        : "=r"(a) : "l"(p));
    return a;
}
__device__ __forceinline__ void cp16(uint32_t saddr, const void* gptr) {
    asm volatile("cp.async.cg.shared.global [%0], [%1], 16;"
                 :: "r"(saddr), "l"(gptr) : "memory");
}
__device__ __forceinline__ void ldsm4(uint32_t r[4], uint32_t addr) {
    asm volatile("ldmatrix.sync.aligned.m8n8.x4.shared.b16 {%0,%1,%2,%3}, [%4];"
                 : "=r"(r[0]), "=r"(r[1]), "=r"(r[2]), "=r"(r[3]) : "r"(addr));
}
__device__ __forceinline__ void ldsm4t(uint32_t r[4], uint32_t addr) {
    asm volatile("ldmatrix.sync.aligned.m8n8.x4.trans.shared.b16 {%0,%1,%2,%3}, [%4];"
                 : "=r"(r[0]), "=r"(r[1]), "=r"(r[2]), "=r"(r[3]) : "r"(addr));
}
__device__ __forceinline__ void mma_f16(float c[4], uint32_t a0, uint32_t a1,
                                        uint32_t a2, uint32_t a3,
                                        uint32_t b0, uint32_t b1) {
    asm volatile(
        "mma.sync.aligned.m16n8k16.row.col.f32.f16.f16.f32 "
        "{%0,%1,%2,%3}, {%4,%5,%6,%7}, {%8,%9}, {%0,%1,%2,%3};\n"
        : "+f"(c[0]), "+f"(c[1]), "+f"(c[2]), "+f"(c[3])
        : "r"(a0), "r"(a1), "r"(a2), "r"(a3), "r"(b0), "r"(b1));
}

// ------------------------- GEMM ---------------------------------------------
// C[M,N] = A[M,K] @ Bt[N,K]^T (+bias). CTA 128x256, K-chunk 32, 4-stage
// cp.async, 8 warps 2(M)x4(N), warp tile 64x64, ldmatrix fragment loads.
// smem rows = 40 halfs (80 B): 16B-aligned cp.async dsts + conflict-free LDSM.

#define STRB   80                         // bytes per smem row
#define A_BYTES (128 * STRB)              // 10240
#define B_BYTES (256 * STRB)              // 20480
#define STG_BYTES (A_BYTES + B_BYTES)     // 30720
#define NSTG   4
#define GSM_BYTES (NSTG * STG_BYTES)      // 122880

template<typename TC>
__global__ __launch_bounds__(256, 1)
void gemm_h(const __half* __restrict__ A, const __half* __restrict__ Bt,
            TC* __restrict__ C, int K, int N, const float* __restrict__ bias)
{
    extern __shared__ __half sh[];
    const uint32_t sb = smem_u32(sh);

    const int t     = threadIdx.x;
    const int lane  = t & 31;
    const int warp  = t >> 5;
    const int warpM = warp >> 2;          // 0..1
    const int warpN = warp & 3;           // 0..3

    const size_t rowBase = (size_t)blockIdx.y * 128;
    const int    colBase = blockIdx.x * 256;
    const int NC = K >> 5;                // >= 4 for all our calls

    float acc[4][8][4];
    #pragma unroll
    for (int mt = 0; mt < 4; mt++)
        #pragma unroll
        for (int nt = 0; nt < 8; nt++)
            #pragma unroll
            for (int i = 0; i < 4; i++) acc[mt][nt][i] = 0.f;

    const __half* Ab = A  + rowBase * K;
    const __half* Bb = Bt + (size_t)colBase * K;

    auto stage = [&](int kc) {
        const uint32_t aD = sb + (kc & (NSTG - 1)) * STG_BYTES;
        const uint32_t bD = aD + A_BYTES;
        const __half* As = Ab + kc * 32;
        const __half* Bs = Bb + kc * 32;
        #pragma unroll
        for (int i = 0; i < 2; i++) {            // A: 512 16B-granules
            int g = i * 256 + t, r = g >> 2, s = g & 3;
            cp16(aD + r * STRB + s * 16, As + (size_t)r * K + s * 8);
        }
        #pragma unroll
        for (int i = 0; i < 4; i++) {            // B: 1024 granules
            int g = i * 256 + t, r = g >> 2, s = g & 3;
            cp16(bD + r * STRB + s * 16, Bs + (size_t)r * K + s * 8);
        }
        asm volatile("cp.async.commit_group;" ::: "memory");
    };

    stage(0); stage(1); stage(2);

    // lane-fixed ldmatrix address pieces
    const int lr    = lane & 15;
    const int aKoff = (lane & 16) ? 16 : 0;              // bytes
    const int bRow  = (lane & 7) + ((lane & 16) ? 8 : 0);
    const int bKoff = (lane & 8) ? 16 : 0;               // bytes

    for (int kc = 0; kc < NC; kc++) {
        if (kc < NC - 2)      asm volatile("cp.async.wait_group 2;" ::: "memory");
        else if (kc == NC - 2) asm volatile("cp.async.wait_group 1;" ::: "memory");
        else                   asm volatile("cp.async.wait_group 0;" ::: "memory");
        __syncthreads();
        if (kc + 3 < NC) stage(kc + 3);

        const uint32_t aB = sb + (kc & (NSTG - 1)) * STG_BYTES;
        const uint32_t bB = aB + A_BYTES;

        #pragma unroll
        for (int ks = 0; ks < 2; ks++) {
            const int k0b = ks * 32;          // 16 halfs
            uint32_t a[4][4], b[4][4];
            #pragma unroll
            for (int mt = 0; mt < 4; mt++)
                ldsm4(a[mt], aB + (warpM * 64 + mt * 16 + lr) * STRB + k0b + aKoff);
            #pragma unroll
            for (int np = 0; np < 4; np++)
                ldsm4(b[np], bB + (warpN * 64 + np * 16 + bRow) * STRB + k0b + bKoff);
            #pragma unroll
            for (int nt = 0; nt < 8; nt++) {
                uint32_t b0 = b[nt >> 1][(nt & 1) * 2];
                uint32_t b1 = b[nt >> 1][(nt & 1) * 2 + 1];
                #pragma unroll
                for (int mt = 0; mt < 4; mt++)
                    mma_f16(acc[mt][nt], a[mt][0], a[mt][1], a[mt][2], a[mt][3],
                            b0, b1);
            }
        }
    }

    // ---- epilogue
    #pragma unroll
    for (int mt = 0; mt < 4; mt++) {
        size_t row = rowBase + warpM * 64 + mt * 16 + (lane >> 2);
        #pragma unroll
        for (int nt = 0; nt < 8; nt++) {
            int col = colBase + warpN * 64 + nt * 8 + 2 * (lane & 3);
            if constexpr (sizeof(TC) == 2) {
                __half* cp = (__half*)C;
                *(uint32_t*)(cp + row * N + col) =
                    pack2h(acc[mt][nt][0], acc[mt][nt][1]);
                *(uint32_t*)(cp + (row + 8) * N + col) =
                    pack2h(acc[mt][nt][2], acc[mt][nt][3]);
            } else {
                float b0 = 0.f, b1 = 0.f;
                if (bias) { b0 = bias[col]; b1 = bias[col + 1]; }
                float* cp = (float*)C;
                *(float2*)(cp + row * N + col) =
                    make_float2(acc[mt][nt][0] + b0, acc[mt][nt][1] + b1);
                *(float2*)(cp + (row + 8) * N + col) =
                    make_float2(acc[mt][nt][2] + b0, acc[mt][nt][3] + b1);
            }
        }
    }
}

// ------------------------- aux kernels --------------------------------------

__global__ void f2h_kernel(const float* __restrict__ in, __half* __restrict__ out,
                           int n4)
{
    int i = blockIdx.x * blockDim.x + threadIdx.x;
    if (i < n4) {
        float4 v = ((const float4*)in)[i];
        ((uint2*)out)[i] = make_uint2(pack2h(v.x, v.y), pack2h(v.z, v.w));
    }
}

__global__ void transpose_h(const float* __restrict__ in, __half* __restrict__ out,
                            int R, int C)
{
    __shared__ float tile[32][33];
    int c0 = blockIdx.x * 32, r0 = blockIdx.y * 32;
    #pragma unroll
    for (int i = threadIdx.y; i < 32; i += 8)
        tile[i][threadIdx.x] = in[(size_t)(r0 + i) * C + c0 + threadIdx.x];
    __syncthreads();
    #pragma unroll
    for (int i = threadIdx.y; i < 32; i += 8)
        out[(size_t)(c0 + i) * R + r0 + threadIdx.x] =
            __float2half_rn(tile[threadIdx.x][i]);
}

// ------------------------- K2: attention core -------------------------------
// One block per (group, head), 4 warps. Q/K/V stored row-major (72-half rows,
// vectorized stores). Fragments via ldmatrix; V B-fragments via ldmatrix.trans.

#define QS 72

__global__ __launch_bounds__(128)
void attn_core(const __half* __restrict__ qkv, __half* __restrict__ o)
{
    __shared__ __half Qs[32 * QS];
    __shared__ __half Ks[32 * QS];
    __shared__ __half Vs[32 * QS];
    __shared__ float  S [32][36];

    const int t    = threadIdx.x;
    const int lane = t & 31;
    const int warp = t >> 5;
    const int g    = blockIdx.x;
    const int h    = g & 7;
    const size_t tokBase = (size_t)(g >> 3) * 32;

    const __half* base = qkv + tokBase * NQKV + h * DH;

    #pragma unroll
    for (int i = 0; i < 4; i++) {
        int idx = i * 128 + t;
        int r   = idx >> 4;             // token 0..31
        int sg  = idx & 15;             // 4-half segment
        const __half* rp = base + (size_t)r * NQKV + sg * 4;
        *(uint2*)(Qs + r * QS + sg * 4) = *(const uint2*)(rp);
        *(uint2*)(Ks + r * QS + sg * 4) = *(const uint2*)(rp + 512);
        *(uint2*)(Vs + r * QS + sg * 4) = *(const uint2*)(rp + 1024);
    }
    __syncthreads();

    const uint32_t qb = smem_u32(Qs);
    const uint32_t kb = smem_u32(Ks);
    const uint32_t vb = smem_u32(Vs);
    const int lr    = lane & 15;
    const int aKoff = (lane & 16) ? 16 : 0;
    const int bRow  = (lane & 7) + ((lane & 16) ? 8 : 0);
    const int bKoff = (lane & 8) ? 16 : 0;
    const int vCoff = (lane & 16) ? 16 : 0;

    // ---- S = Q K^T (4 k16 steps)
    const int mt  = warp & 1;
    const int ntb = (warp >> 1) * 2;
    float sacc[2][4] = {{0.f,0.f,0.f,0.f},{0.f,0.f,0.f,0.f}};
    #pragma unroll
    for (int ks = 0; ks < 4; ks++) {
        const int k0b = ks * 32;
        uint32_t a[4], b[4];
        ldsm4(a, qb + (mt * 16 + lr) * (QS * 2) + k0b + aKoff);
        ldsm4(b, kb + (ntb * 8 + bRow) * (QS * 2) + k0b + bKoff);
        mma_f16(sacc[0], a[0], a[1], a[2], a[3], b[0], b[1]);
        mma_f16(sacc[1], a[0], a[1], a[2], a[3], b[2], b[3]);
    }
    #pragma unroll
    for (int n = 0; n < 2; n++) {
        int row = mt * 16 + (lane >> 2);
        int col = (ntb + n) * 8 + 2 * (lane & 3);
        S[row    ][col    ] = sacc[n][0] * ATT_SCALE;
        S[row    ][col + 1] = sacc[n][1] * ATT_SCALE;
        S[row + 8][col    ] = sacc[n][2] * ATT_SCALE;
        S[row + 8][col + 1] = sacc[n][3] * ATT_SCALE;
    }
    __syncthreads();

    // ---- softmax: warp w -> rows 8w..8w+7, lane = column
    #pragma unroll
    for (int rr = 0; rr < 8; rr++) {
        int row = warp * 8 + rr;
        float v = S[row][lane];
        float m = v;
        #pragma unroll
        for (int off = 16; off; off >>= 1) m = fmaxf(m, __shfl_xor_sync(~0u, m, off));
        float e = __expf(v - m);
        float s = e;
        #pragma unroll
        for (int off = 16; off; off >>= 1) s += __shfl_xor_sync(~0u, s, off);
        S[row][lane] = e / s;
    }
    __syncthreads();

    // ---- O = P V (2 k16 steps, V via ldmatrix.trans)
    const int dBase = (warp >> 1) * 32;
    float oacc[4][4];
    #pragma unroll
    for (int n = 0; n < 4; n++)
        #pragma unroll
        for (int i = 0; i < 4; i++) oacc[n][i] = 0.f;

    #pragma unroll
    for (int ks = 0; ks < 2; ks++) {
        const int j0 = ks * 16;
        int r0 = mt * 16 + (lane >> 2);
        int c  = j0 + (lane & 3) * 2;
        uint32_t a0 = pack2h(S[r0    ][c    ], S[r0    ][c + 1]);
        uint32_t a1 = pack2h(S[r0 + 8][c    ], S[r0 + 8][c + 1]);
        uint32_t a2 = pack2h(S[r0    ][c + 8], S[r0    ][c + 9]);
        uint32_t a3 = pack2h(S[r0 + 8][c + 8], S[r0 + 8][c + 9]);
        #pragma unroll
        for (int hf = 0; hf < 2; hf++) {
            uint32_t b[4];
            int dA = dBase + hf * 16;
            ldsm4t(b, vb + (j0 + lr) * (QS * 2) + dA * 2 + vCoff);
            mma_f16(oacc[hf * 2    ], a0, a1, a2, a3, b[0], b[1]);
            mma_f16(oacc[hf * 2 + 1], a0, a1, a2, a3, b[2], b[3]);
        }
    }

    __half* obase = o + tokBase * INNER + h * DH;
    const int nt4 = (warp >> 1) * 4;
    #pragma unroll
    for (int n = 0; n < 4; n++) {
        int row = mt * 16 + (lane >> 2);
        int col = (nt4 + n) * 8 + 2 * (lane & 3);
        *(uint32_t*)(obase + (size_t)row * INNER + col) =
            pack2h(oacc[n][0], oacc[n][1]);
        *(uint32_t*)(obase + (size_t)(row + 8) * INNER + col) =
            pack2h(oacc[n][2], oacc[n][3]);
    }
}

// ------------------------- launch -------------------------------------------

extern "C" void kernel_launch(void* const* d_in, const int* in_sizes, int n_in,
                              void* d_out, int out_size)
{
    const float* x     = (const float*)d_in[0];
    const float* W_qkv = (const float*)d_in[1];
    const float* W_out = (const float*)d_in[2];
    const float* b_out = (const float*)d_in[3];
    float* out = (float*)d_out;

    __half *xh, *qkv, *att, *wqT, *woT;
    cudaGetSymbolAddress((void**)&xh,  g_xh);
    cudaGetSymbolAddress((void**)&qkv, g_qkv);
    cudaGetSymbolAddress((void**)&att, g_attn);
    cudaGetSymbolAddress((void**)&wqT, g_WqkvT);
    cudaGetSymbolAddress((void**)&woT, g_WoutT);

    cudaFuncSetAttribute(gemm_h<__half>,
                         cudaFuncAttributeMaxDynamicSharedMemorySize, GSM_BYTES);
    cudaFuncSetAttribute(gemm_h<float>,
                         cudaFuncAttributeMaxDynamicSharedMemorySize, GSM_BYTES);

    // K0: x -> fp16
    const int n4 = TOKENS * DIMX / 4;
    f2h_kernel<<<n4 / 256, 256>>>(x, xh, n4);

    // weights -> [N,K] fp16
    transpose_h<<<dim3(NQKV / 32, DIMX / 32), dim3(32, 8)>>>(W_qkv, wqT, DIMX, NQKV);
    transpose_h<<<dim3(DIMX / 32, INNER / 32), dim3(32, 8)>>>(W_out, woT, INNER, DIMX);

    // K1: qkv = xh @ W_qkv  (M=131072, K=256, N=1536)
    gemm_h<__half><<<dim3(NQKV / 256, TOKENS / 128), 256, GSM_BYTES>>>(
        xh, wqT, qkv, DIMX, NQKV, nullptr);

    // K2: attention
    attn_core<<<GROUPS * HEADS, 128>>>(qkv, att);

    // K3: out = att @ W_out + b  (M=131072, K=512, N=256)
    gemm_h<float><<<dim3(DIMX / 256, TOKENS / 128), 256, GSM_BYTES>>>(
        att, woT, out, INNER, DIMX, b_out);
}